// round 14
// baseline (speedup 1.0000x reference)
#include <cuda_runtime.h>
#include <cuda_bf16.h>

// Problem constants
#define S_LEN  2048
#define DMODEL 4096
#define NH     32
#define NHK    8
#define HD     128
#define TCACHE 2048

// ---------------------------------------------------------------------------
// Scratch (allocation-free). q/k/v/ao hold tf32 bits. Weights stored
// TRANSPOSED [N][K] (for [n][k] smem layout feeding ldmatrix B-fragments).
// ---------------------------------------------------------------------------
__device__ unsigned g_q [S_LEN * DMODEL];
__device__ unsigned g_k [S_LEN * NHK * HD];
__device__ unsigned g_v [S_LEN * NHK * HD];
__device__ unsigned g_ao[S_LEN * DMODEL];
__device__ unsigned g_xc [S_LEN * DMODEL];
__device__ unsigned g_wqc[DMODEL * DMODEL];      // [N=4096][K=4096]
__device__ unsigned g_wkc[NHK * HD * DMODEL];    // [N=1024][K=4096]
__device__ unsigned g_wvc[NHK * HD * DMODEL];
__device__ unsigned g_woc[DMODEL * DMODEL];
__device__ unsigned g_ckc[TCACHE * NHK * HD];
__device__ unsigned g_cvc[TCACHE * NHK * HD];

// ---------------------------------------------------------------------------
// Helpers
// ---------------------------------------------------------------------------
__device__ __forceinline__ unsigned f2tf(float f) {
  unsigned u;
  asm("cvt.rn.tf32.f32 %0, %1;" : "=r"(u) : "f"(f));
  return u;
}
__device__ __forceinline__ unsigned smem_u32(const void* p) {
  unsigned a;
  asm("{ .reg .u64 t; cvta.to.shared.u64 t, %1; cvt.u32.u64 %0, t; }"
      : "=r"(a) : "l"(p));
  return a;
}
__device__ __forceinline__ void cp16(unsigned dst, const void* src) {
  asm volatile("cp.async.cg.shared.global [%0], [%1], 16;"
               :: "r"(dst), "l"(src));
}
__device__ __forceinline__ void mma_tf32(float* c, const unsigned* a,
                                         const unsigned* b) {
  asm volatile(
    "mma.sync.aligned.m16n8k8.row.col.f32.tf32.tf32.f32 "
    "{%0,%1,%2,%3}, {%4,%5,%6,%7}, {%8,%9}, {%0,%1,%2,%3};"
    : "+f"(c[0]), "+f"(c[1]), "+f"(c[2]), "+f"(c[3])
    : "r"(a[0]), "r"(a[1]), "r"(a[2]), "r"(a[3]), "r"(b[0]), "r"(b[1]));
}
// ldmatrix x4: loads 4 8x4-b32 matrices. Address = per-thread row ptr.
__device__ __forceinline__ void ldsm4(unsigned* r, unsigned addr) {
  asm volatile("ldmatrix.sync.aligned.m8n8.x4.shared.b16 {%0,%1,%2,%3}, [%4];"
    : "=r"(r[0]), "=r"(r[1]), "=r"(r[2]), "=r"(r[3]) : "r"(addr));
}

// ---------------------------------------------------------------------------
// Single merged conversion kernel (one launch):
//   [0,8192)       elementwise x
//   [8192,10240)   elementwise cache_k
//   [10240,12288)  elementwise cache_v
//   [12288,28672)  transpose wq  (128x128 32-blocks)
//   [28672,32768)  transpose wk  (32x128)
//   [32768,36864)  transpose wv  (32x128)
//   [36864,53248)  transpose wo  (128x128)
// ---------------------------------------------------------------------------
__global__ __launch_bounds__(256)
void conv_merged(const float* __restrict__ x, const float* __restrict__ ck,
                 const float* __restrict__ cv,
                 const float* __restrict__ wq, const float* __restrict__ wk,
                 const float* __restrict__ wv, const float* __restrict__ wo,
                 unsigned* __restrict__ xc, unsigned* __restrict__ ckc,
                 unsigned* __restrict__ cvc,
                 unsigned* __restrict__ wqc, unsigned* __restrict__ wkc,
                 unsigned* __restrict__ wvc, unsigned* __restrict__ woc) {
  int bid = blockIdx.x;
  if (bid < 12288) {
    const float* in; unsigned* out; size_t base;
    if (bid < 8192)       { in = x;  out = xc;  base = (size_t)bid * 1024; }
    else if (bid < 10240) { in = ck; out = ckc; base = (size_t)(bid - 8192) * 1024; }
    else                  { in = cv; out = cvc; base = (size_t)(bid - 10240) * 1024; }
    size_t i = base + threadIdx.x * 4;
    float4 v = *(const float4*)(in + i);
    uint4 o;
    o.x = f2tf(v.x); o.y = f2tf(v.y); o.z = f2tf(v.z); o.w = f2tf(v.w);
    *(uint4*)(out + i) = o;
    return;
  }
  __shared__ unsigned t[32][33];
  int b = bid - 12288;
  const float* in; unsigned* out; int N, bx, by;
  if (b < 16384)      { in = wq; out = wqc; N = DMODEL;  bx = b & 127; by = b >> 7; }
  else if (b < 20480) { int c = b - 16384; in = wk; out = wkc; N = NHK * HD; bx = c & 31; by = c >> 5; }
  else if (b < 24576) { int c = b - 20480; in = wv; out = wvc; N = NHK * HD; bx = c & 31; by = c >> 5; }
  else                { int c = b - 24576; in = wo; out = woc; N = DMODEL;  bx = c & 127; by = c >> 7; }
  int n0 = bx * 32, k0 = by * 32;
  int tx = threadIdx.x & 31, ty = threadIdx.x >> 5;
  #pragma unroll
  for (int i = 0; i < 4; i++)
    t[ty + 8 * i][tx] = f2tf(in[(size_t)(k0 + ty + 8 * i) * N + n0 + tx]);
  __syncthreads();
  #pragma unroll
  for (int i = 0; i < 4; i++)
    out[(size_t)(n0 + ty + 8 * i) * DMODEL + k0 + tx] = t[tx][ty + 8 * i];
}

// ---------------------------------------------------------------------------
// Tensor-core GEMM: 128x128 CTA tile, BK=32, 3-stage cp.async, occ 2,
// ldmatrix fragment loads with register double-buffering over kk.
// ---------------------------------------------------------------------------
#define ASTRIDE 36
#define ABUF (128 * ASTRIDE)
#define BBUF (128 * ASTRIDE)
#define GEMM_SMEM ((3 * ABUF + 3 * BBUF) * 4)   // 110592 bytes

__device__ __forceinline__
void gemm_body(const unsigned* __restrict__ A, const unsigned* __restrict__ Bt,
               float* __restrict__ C, int N, int K,
               const float* __restrict__ rope, int bm, int bn, unsigned* gsm,
               bool cvt_out) {
  unsigned* AsB = gsm;                 // [3][128][36]
  unsigned* BsB = gsm + 3 * ABUF;      // [3][128][36]  ([n][k])
  int tid  = threadIdx.x;
  int wid  = tid >> 5, lane = tid & 31;
  int wm   = (wid >> 2) * 64;
  int wn   = (wid & 3) * 32;
  int gr   = lane >> 2;
  int tg   = lane & 3;
  int rsel = lane & 7, matid = lane >> 3;

  int arow = tid >> 1, acol = (tid & 1) * 16;

  auto issue_copy = [&](int k0, int buf) {
    unsigned adst = smem_u32(AsB + buf * ABUF + arow * ASTRIDE + acol);
    const unsigned* asrc = A + (size_t)(bm + arow) * K + k0 + acol;
    #pragma unroll
    for (int i = 0; i < 4; i++) cp16(adst + 16 * i, asrc + 4 * i);
    unsigned bdst = smem_u32(BsB + buf * BBUF + arow * ASTRIDE + acol);
    const unsigned* bsrc = Bt + (size_t)(bn + arow) * K + k0 + acol;
    #pragma unroll
    for (int i = 0; i < 4; i++) cp16(bdst + 16 * i, bsrc + 4 * i);
    asm volatile("cp.async.commit_group;" ::: "memory");
  };

  unsigned aA = smem_u32(AsB) +
      4 * ((wm + ((matid & 1) << 3) + rsel) * ASTRIDE + ((matid >> 1) << 2));
  unsigned bB = smem_u32(BsB) +
      4 * ((wn + ((matid >> 1) << 3) + rsel) * ASTRIDE + ((matid & 1) << 2));

  float acc[4][4][4] = {};
  int nit = K / 32;
  issue_copy(0, 0);
  issue_copy(32, 1);

  int buf = 0;
  for (int it = 0; it < nit; it++) {
    if (it < nit - 1)
      asm volatile("cp.async.wait_group 1;" ::: "memory");
    else
      asm volatile("cp.async.wait_group 0;" ::: "memory");
    __syncthreads();
    if (it + 2 < nit) issue_copy((it + 2) * 32, (it + 2) % 3);

    unsigned aAb = aA + buf * (ABUF * 4);
    unsigned bBb = bB + buf * (BBUF * 4);

    unsigned af[2][4][4], bf[2][2][4];
    #pragma unroll
    for (int mt = 0; mt < 4; mt++)
      ldsm4(af[0][mt], aAb + mt * (16 * ASTRIDE * 4));
    #pragma unroll
    for (int np = 0; np < 2; np++)
      ldsm4(bf[0][np], bBb + np * (16 * ASTRIDE * 4));

    #pragma unroll
    for (int k8 = 0; k8 < 4; k8++) {
      int cb = k8 & 1, nb = cb ^ 1;
      if (k8 < 3) {
        int kk = (k8 + 1) * 8;
        #pragma unroll
        for (int mt = 0; mt < 4; mt++)
          ldsm4(af[nb][mt], aAb + mt * (16 * ASTRIDE * 4) + kk * 4);
        #pragma unroll
        for (int np = 0; np < 2; np++)
          ldsm4(bf[nb][np], bBb + np * (16 * ASTRIDE * 4) + kk * 4);
      }
      #pragma unroll
      for (int mt = 0; mt < 4; mt++)
        #pragma unroll
        for (int nt = 0; nt < 4; nt++)
          mma_tf32(acc[mt][nt], af[cb][mt], &bf[cb][nt >> 1][(nt & 1) * 2]);
    }
    buf = (buf + 1) % 3;
  }

  #pragma unroll
  for (int mt = 0; mt < 4; mt++) {
    #pragma unroll
    for (int half = 0; half < 2; half++) {
      int m = bm + wm + mt * 16 + gr + half * 8;
      const float* rp = rope ? (rope + (size_t)m * HD) : (const float*)0;
      #pragma unroll
      for (int nt = 0; nt < 4; nt++) {
        int n = bn + wn + nt * 8 + 2 * tg;
        float x = acc[mt][nt][half * 2 + 0];
        float y = acc[mt][nt][half * 2 + 1];
        if (rp) {
          x *= rp[n & (HD - 1)];
          y *= rp[(n + 1) & (HD - 1)];
        }
        float2 v;
        if (cvt_out) {
          v.x = __uint_as_float(f2tf(x));
          v.y = __uint_as_float(f2tf(y));
        } else {
          v.x = x; v.y = y;
        }
        *(float2*)&C[(size_t)m * N + n] = v;
      }
    }
  }
}

// Fused QKV, packed grid: [0,512) Q (32nb x 16mb), [512,640) K, [640,768) V
__global__ __launch_bounds__(256, 2)
void gemm_qkv(const unsigned* __restrict__ x,
              const unsigned* __restrict__ wq, const unsigned* __restrict__ wk,
              const unsigned* __restrict__ wv,
              unsigned* __restrict__ q, unsigned* __restrict__ k,
              unsigned* __restrict__ v, const float* __restrict__ rope) {
  extern __shared__ unsigned gsm[];
  int bid = blockIdx.x;
  const unsigned* B; unsigned* C; int N; const float* rp; int bx, by;
  if (bid < 512) {
    B = wq; C = q; N = DMODEL; rp = rope;
    bx = bid & 31; by = bid >> 5;
  } else if (bid < 640) {
    int b2 = bid - 512;
    B = wk; C = k; N = NHK * HD; rp = rope;
    bx = b2 & 7; by = b2 >> 3;
  } else {
    int b2 = bid - 640;
    B = wv; C = v; N = NHK * HD; rp = (const float*)0;
    bx = b2 & 7; by = b2 >> 3;
  }
  gemm_body(x, B, (float*)C, N, DMODEL, rp, by * 128, bx * 128, gsm, true);
}

__global__ __launch_bounds__(256, 2)
void gemm_mma(const unsigned* __restrict__ A, const unsigned* __restrict__ Bt,
              float* __restrict__ C, int N, int K) {
  extern __shared__ unsigned gsm[];
  gemm_body(A, Bt, C, N, K, (const float*)0,
            blockIdx.y * 128, blockIdx.x * 128, gsm, false);
}

// ---------------------------------------------------------------------------
// Tensor-core flash attention, 256 threads, ldmatrix, GQA 2-heads/CTA,
// register double-buffered S-loop AND PV-loop fragments.
// ---------------------------------------------------------------------------
#define BQ  128
#define BKV 64
#define AQS 0
#define AKS 16896
#define KBUF 8448
#define AVS 33792
#define APS 42496
#define AMS 51200
#define ALS 51328
#define AAS 51456
#define ASX 51584
#define ASS 51840
#define ATTN_SMEM_BYTES (52096 * 4)

__global__ __launch_bounds__(256, 1)
void attn_mma(const unsigned* __restrict__ Q, const unsigned* __restrict__ Kn,
              const unsigned* __restrict__ Vn, const unsigned* __restrict__ cK,
              const unsigned* __restrict__ cV, unsigned* __restrict__ Out) {
  extern __shared__ unsigned sm_u[];
  float* sm_f = reinterpret_cast<float*>(sm_u);
  unsigned* Qs  = sm_u + AQS;
  unsigned* KsA = sm_u + AKS;
  unsigned* Vs  = sm_u + AVS;
  unsigned* Pu  = sm_u + APS;
  float* m_s  = sm_f + AMS;
  float* l_s  = sm_f + ALS;
  float* al_s = sm_f + AAS;
  float* smax = sm_f + ASX;   // [2][128]
  float* ssum = sm_f + ASS;   // [2][128]

  int tid = threadIdx.x;
  int bid = blockIdx.x;
  int qt = 31 - (bid >> 4);             // heaviest q-tile first
  int sub = bid & 15;
  int hk = sub >> 1;
  int ha = hk * 4 + (sub & 1) * 2;      // first head of the pair
  int q0 = qt * 64;                     // 64-query range per head
  int wid = tid >> 5, lane = tid & 31;
  int gr = lane >> 2, tg = lane & 3;
  int wm = (wid >> 1) * 32;
  int wn = wid & 1;
  int rsel = lane & 7, matid = lane >> 3;
  const float scale = 0.08838834764831845f;

  unsigned sbase = smem_u32(sm_u);
  unsigned qA = sbase + 4 * (AQS +
      (wm + ((matid & 1) << 3) + rsel) * 132 + ((matid >> 1) << 2));
  unsigned kB = sbase + 4 * (AKS +
      (wn * 32 + ((matid >> 1) << 3) + rsel) * 132 + ((matid & 1) << 2));
  unsigned vB = sbase + 4 * (AVS +
      (wn * 64 + ((matid >> 1) << 3) + rsel) * 68 + ((matid & 1) << 2));
  unsigned pA = sbase + 4 * (APS +
      (wm + ((matid & 1) << 3) + rsel) * 68 + ((matid >> 1) << 2));

  // ---- load Q tile: rows 0-63 head ha, rows 64-127 head ha+1 ----
  #pragma unroll
  for (int i = 0; i < 16; i++) {
    int lin = tid + i * 256;
    int r = lin & 127, d16 = lin >> 7;
    int head = ha + (r >> 6);
    int qg = q0 + (r & 63);
    uint4 v = *(const uint4*)&Q[(size_t)qg * DMODEL + head * HD + d16 * 4];
    *(uint4*)&Qs[r * 132 + d16 * 4] = v;
  }
  if (tid < 128) { m_s[tid] = -1e30f; l_s[tid] = 0.0f; }

  // ---- load K tile 0 into Ks[0] (natural [t][132]) ----
  #pragma unroll
  for (int i = 0; i < 8; i++) {
    int lin = tid + i * 256;
    int t = lin >> 5, d16 = lin & 31;
    uint4 v = *(const uint4*)&cK[(size_t)t * (NHK * HD) + hk * HD + d16 * 4];
    *(uint4*)&KsA[t * 132 + d16 * 4] = v;
  }

  float o[2][8][4] = {};
  int ntiles = 33 + qt;
  int cur = 0;

  for (int tile = 0; tile < ntiles; tile++) {
    int t0 = tile * BKV;
    bool isnew = (t0 >= TCACHE);
    const unsigned* vb = isnew ? Vn : cV;
    int tr0 = t0 & (TCACHE - 1);
    __syncthreads();   // P/Vs free; stats final; Ks[cur^1] free

    // ---- prefetch V(tile) and K(tile+1) into registers ----
    uint4 vreg[8], kreg[8];
    #pragma unroll
    for (int i = 0; i < 8; i++) {
      int lin = tid + i * 256;
      int t = lin & 63, d4 = lin >> 6;
      vreg[i] = *(const uint4*)&vb[(size_t)(tr0 + t) * (NHK * HD) + hk * HD + d4 * 4];
    }
    bool havek = (tile + 1 < ntiles);
    if (havek) {
      int t1 = t0 + BKV;
      const unsigned* kb2 = (t1 >= TCACHE) ? Kn : cK;
      int tr1 = t1 & (TCACHE - 1);
      #pragma unroll
      for (int i = 0; i < 8; i++) {
        int lin = tid + i * 256;
        int t = lin >> 5, d16 = lin & 31;
        kreg[i] = *(const uint4*)&kb2[(size_t)(tr1 + t) * (NHK * HD) + hk * HD + d16 * 4];
      }
    }

    // ---- S = Q K^T : warp tile 32q x 32t (ldmatrix, reg double-buffered) ----
    float s[2][4][4] = {};
    unsigned kBb = kB + cur * (KBUF * 4);
    {
      unsigned af[2][2][4], bf[2][2][4];
      ldsm4(af[0][0], qA);
      ldsm4(af[0][1], qA + 16 * 132 * 4);
      ldsm4(bf[0][0], kBb);
      ldsm4(bf[0][1], kBb + 16 * 132 * 4);
      #pragma unroll
      for (int k8 = 0; k8 < 16; k8++) {
        int cb = k8 & 1, nb = cb ^ 1;
        if (k8 < 15) {
          int kk = (k8 + 1) * 8;
          ldsm4(af[nb][0], qA + kk * 4);
          ldsm4(af[nb][1], qA + 16 * 132 * 4 + kk * 4);
          ldsm4(bf[nb][0], kBb + kk * 4);
          ldsm4(bf[nb][1], kBb + 16 * 132 * 4 + kk * 4);
        }
        #pragma unroll
        for (int mt = 0; mt < 2; mt++)
          #pragma unroll
          for (int nt = 0; nt < 4; nt++)
            mma_tf32(s[mt][nt], af[cb][mt], &bf[cb][nt >> 1][(nt & 1) * 2]);
      }
    }

    // ---- store V tile ([d][t]) ----
    #pragma unroll
    for (int i = 0; i < 8; i++) {
      int lin = tid + i * 256;
      int t = lin & 63, d4 = lin >> 6;
      Vs[(d4 * 4 + 0) * 68 + t] = vreg[i].x;
      Vs[(d4 * 4 + 1) * 68 + t] = vreg[i].y;
      Vs[(d4 * 4 + 2) * 68 + t] = vreg[i].z;
      Vs[(d4 * 4 + 3) * 68 + t] = vreg[i].w;
    }

    // ---- scale + causal mask (row r -> query q0 + (r&63)) ----
    #pragma unroll
    for (int mt = 0; mt < 2; mt++)
      #pragma unroll
      for (int nt = 0; nt < 4; nt++) {
        int c0 = wn * 32 + nt * 8 + 2 * tg;
        #pragma unroll
        for (int half = 0; half < 2; half++) {
          int r = wm + mt * 16 + gr + half * 8;
          int qg = q0 + (r & 63);
          float x = s[mt][nt][half * 2 + 0] * scale;
          float y = s[mt][nt][half * 2 + 1] * scale;
          if (isnew) {
            if (t0 + c0     - TCACHE > qg) x = -1e30f;
            if (t0 + c0 + 1 - TCACHE > qg) y = -1e30f;
          }
          s[mt][nt][half * 2 + 0] = x;
          s[mt][nt][half * 2 + 1] = y;
        }
      }

    // ---- row max: local, shfl over tg, publish ----
    float pm[2][2], mold[2][2];
    #pragma unroll
    for (int mt = 0; mt < 2; mt++)
      #pragma unroll
      for (int hf = 0; hf < 2; hf++) {
        float m1 = -1e30f;
        #pragma unroll
        for (int nt = 0; nt < 4; nt++)
          m1 = fmaxf(m1, fmaxf(s[mt][nt][hf * 2], s[mt][nt][hf * 2 + 1]));
        pm[mt][hf] = m1;
      }
    #pragma unroll
    for (int mt = 0; mt < 2; mt++)
      #pragma unroll
      for (int hf = 0; hf < 2; hf++) {
        pm[mt][hf] = fmaxf(pm[mt][hf], __shfl_xor_sync(0xffffffffu, pm[mt][hf], 1));
        pm[mt][hf] = fmaxf(pm[mt][hf], __shfl_xor_sync(0xffffffffu, pm[mt][hf], 2));
        int row = wm + mt * 16 + hf * 8 + gr;
        mold[mt][hf] = m_s[row];
        if (tg == 0) smax[wn * 128 + row] = pm[mt][hf];
      }
    __syncthreads();   // smax ready; Vs complete

    // ---- exp in registers, P as tf32, partial sums ----
    float al[2][2], mn[2][2], ps[2][2];
    #pragma unroll
    for (int mt = 0; mt < 2; mt++)
      #pragma unroll
      for (int hf = 0; hf < 2; hf++) {
        int row = wm + mt * 16 + hf * 8 + gr;
        float mnew = fmaxf(mold[mt][hf],
                           fmaxf(smax[row], smax[128 + row]));
        mn[mt][hf] = mnew;
        al[mt][hf] = __expf(mold[mt][hf] - mnew);
        float sum = 0.0f;
        #pragma unroll
        for (int nt = 0; nt < 4; nt++) {
          int c0 = wn * 32 + nt * 8 + 2 * tg;
          float p0 = __expf(s[mt][nt][hf * 2 + 0] - mnew);
          float p1 = __expf(s[mt][nt][hf * 2 + 1] - mnew);
          sum += p0 + p1;
          uint2 w; w.x = f2tf(p0); w.y = f2tf(p1);
          *(uint2*)&Pu[row * 68 + c0] = w;
        }
        ps[mt][hf] = sum;
      }
    #pragma unroll
    for (int mt = 0; mt < 2; mt++)
      #pragma unroll
      for (int hf = 0; hf < 2; hf++) {
        ps[mt][hf] += __shfl_xor_sync(0xffffffffu, ps[mt][hf], 1);
        ps[mt][hf] += __shfl_xor_sync(0xffffffffu, ps[mt][hf], 2);
        int row = wm + mt * 16 + hf * 8 + gr;
        if (tg == 0) {
          ssum[wn * 128 + row] = ps[mt][hf];
          if (wn == 0) { al_s[row] = al[mt][hf]; m_s[row] = mn[mt][hf]; }
        }
      }

    // ---- store K(tile+1) into Ks[cur^1] ----
    if (havek) {
      unsigned* Kx = KsA + (cur ^ 1) * KBUF;
      #pragma unroll
      for (int i = 0; i < 8; i++) {
        int lin = tid + i * 256;
        int t = lin >> 5, d16 = lin & 31;
        *(uint4*)&Kx[t * 132 + d16 * 4] = kreg[i];
      }
    }
    __syncthreads();   // P, ssum, alpha, next K ready

    // ---- l update (one lane per row) ----
    if (wn == 0 && tg == 0) {
      #pragma unroll
      for (int mt = 0; mt < 2; mt++)
        #pragma unroll
        for (int hf = 0; hf < 2; hf++) {
          int row = wm + mt * 16 + hf * 8 + gr;
          l_s[row] = l_s[row] * al[mt][hf] + ssum[row] + ssum[128 + row];
        }
    }

    // ---- rescale O by alpha, then O += P V (reg double-buffered) ----
    float alv[2][2];
    alv[0][0] = al_s[wm + gr];
    alv[0][1] = al_s[wm + 8 + gr];
    alv[1][0] = al_s[wm + 16 + gr];
    alv[1][1] = al_s[wm + 24 + gr];
    #pragma unroll
    for (int mt = 0; mt < 2; mt++)
      #pragma unroll
      for (int nt = 0; nt < 8; nt++) {
        o[mt][nt][0] *= alv[mt][0];
        o[mt][nt][1] *= alv[mt][0];
        o[mt][nt][2] *= alv[mt][1];
        o[mt][nt][3] *= alv[mt][1];
      }
    {
      unsigned af[2][2][4], bf[2][4][4];
      ldsm4(af[0][0], pA);
      ldsm4(af[0][1], pA + 16 * 68 * 4);
      #pragma unroll
      for (int np = 0; np < 4; np++)
        ldsm4(bf[0][np], vB + np * (16 * 68 * 4));
      #pragma unroll
      for (int k8 = 0; k8 < 8; k8++) {
        int cb = k8 & 1, nb = cb ^ 1;
        if (k8 < 7) {
          int kk = (k8 + 1) * 8;
          ldsm4(af[nb][0], pA + kk * 4);
          ldsm4(af[nb][1], pA + 16 * 68 * 4 + kk * 4);
          #pragma unroll
          for (int np = 0; np < 4; np++)
            ldsm4(bf[nb][np], vB + np * (16 * 68 * 4) + kk * 4);
        }
        #pragma unroll
        for (int mt = 0; mt < 2; mt++)
          #pragma unroll
          for (int nt = 0; nt < 8; nt++)
            mma_tf32(o[mt][nt], af[cb][mt], &bf[cb][nt >> 1][(nt & 1) * 2]);
      }
    }
    cur ^= 1;
  }
  __syncthreads();   // final l_s visible

  // ---- epilogue: O /= l, write tf32 bits (row r -> head ha+(r>>6)) ----
  float inv[2][2];
  inv[0][0] = 1.0f / l_s[wm + gr];
  inv[0][1] = 1.0f / l_s[wm + 8 + gr];
  inv[1][0] = 1.0f / l_s[wm + 16 + gr];
  inv[1][1] = 1.0f / l_s[wm + 24 + gr];
  #pragma unroll
  for (int mt = 0; mt < 2; mt++)
    #pragma unroll
    for (int half = 0; half < 2; half++) {
      int r = wm + mt * 16 + gr + half * 8;
      int head = ha + (r >> 6);
      int qg = q0 + (r & 63);
      #pragma unroll
      for (int nt = 0; nt < 8; nt++) {
        int c = wn * 64 + nt * 8 + 2 * tg;
        uint2 w;
        w.x = f2tf(o[mt][nt][half * 2 + 0] * inv[mt][half]);
        w.y = f2tf(o[mt][nt][half * 2 + 1] * inv[mt][half]);
        *(uint2*)&Out[(size_t)qg * DMODEL + head * HD + c] = w;
      }
    }
}

// ---------------------------------------------------------------------------
// Launch
// ---------------------------------------------------------------------------
extern "C" void kernel_launch(void* const* d_in, const int* in_sizes, int n_in,
                              void* d_out, int out_size) {
  const float* x       = (const float*)d_in[0];
  const float* rope    = (const float*)d_in[1];
  // d_in[2] = mask: unused (causality implemented exactly in-kernel)
  const float* cache_k = (const float*)d_in[3];
  const float* cache_v = (const float*)d_in[4];
  const float* wq      = (const float*)d_in[5];
  const float* wk      = (const float*)d_in[6];
  const float* wv      = (const float*)d_in[7];
  const float* wo      = (const float*)d_in[8];
  float* out = (float*)d_out;

  unsigned *q, *k, *v, *ao, *xc, *wqc, *wkc, *wvc, *woc, *ckc, *cvc;
  cudaGetSymbolAddress((void**)&q,   g_q);
  cudaGetSymbolAddress((void**)&k,   g_k);
  cudaGetSymbolAddress((void**)&v,   g_v);
  cudaGetSymbolAddress((void**)&ao,  g_ao);
  cudaGetSymbolAddress((void**)&xc,  g_xc);
  cudaGetSymbolAddress((void**)&wqc, g_wqc);
  cudaGetSymbolAddress((void**)&wkc, g_wkc);
  cudaGetSymbolAddress((void**)&wvc, g_wvc);
  cudaGetSymbolAddress((void**)&woc, g_woc);
  cudaGetSymbolAddress((void**)&ckc, g_ckc);
  cudaGetSymbolAddress((void**)&cvc, g_cvc);

  cudaFuncSetAttribute(gemm_qkv, cudaFuncAttributeMaxDynamicSharedMemorySize,
                       GEMM_SMEM);
  cudaFuncSetAttribute(gemm_mma, cudaFuncAttributeMaxDynamicSharedMemorySize,
                       GEMM_SMEM);
  cudaFuncSetAttribute(attn_mma, cudaFuncAttributeMaxDynamicSharedMemorySize,
                       ATTN_SMEM_BYTES);

  // All conversions in one launch
  conv_merged<<<53248, 256>>>(x, cache_k, cache_v, wq, wk, wv, wo,
                              xc, ckc, cvc, wqc, wkc, wvc, woc);

  // Fused QKV projection (packed: 512 Q + 128 K + 128 V)
  gemm_qkv<<<768, 256, GEMM_SMEM>>>(xc, wqc, wkc, wvc, q, k, v, rope);

  // Flash attention (GQA 2-heads/CTA, heaviest q-tiles first)
  attn_mma<<<512, 256, ATTN_SMEM_BYTES>>>(q, k, v, ckc, cvc, ao);

  // Output projection
  gemm_mma<<<dim3(DMODEL / 128, S_LEN / 128), 256, GEMM_SMEM>>>(
      ao, woc, out, DMODEL, DMODEL);
}

// round 15
// speedup vs baseline: 1.5422x; 1.5422x over previous
#include <cuda_runtime.h>
#include <cuda_bf16.h>

// Problem constants
#define S_LEN  2048
#define DMODEL 4096
#define NH     32
#define NHK    8
#define HD     128
#define TCACHE 2048

// ---------------------------------------------------------------------------
// Scratch (allocation-free). q/k/v/ao hold tf32 bits. Weights stored
// TRANSPOSED [N][K] (for [n][k] smem layout feeding ldmatrix B-fragments).
// ---------------------------------------------------------------------------
__device__ unsigned g_q [S_LEN * DMODEL];
__device__ unsigned g_k [S_LEN * NHK * HD];
__device__ unsigned g_v [S_LEN * NHK * HD];
__device__ unsigned g_ao[S_LEN * DMODEL];
__device__ unsigned g_xc [S_LEN * DMODEL];
__device__ unsigned g_wqc[DMODEL * DMODEL];      // [N=4096][K=4096]
__device__ unsigned g_wkc[NHK * HD * DMODEL];    // [N=1024][K=4096]
__device__ unsigned g_wvc[NHK * HD * DMODEL];
__device__ unsigned g_woc[DMODEL * DMODEL];
__device__ unsigned g_ckc[TCACHE * NHK * HD];
__device__ unsigned g_cvc[TCACHE * NHK * HD];

// ---------------------------------------------------------------------------
// Helpers
// ---------------------------------------------------------------------------
__device__ __forceinline__ unsigned f2tf(float f) {
  unsigned u;
  asm("cvt.rn.tf32.f32 %0, %1;" : "=r"(u) : "f"(f));
  return u;
}
__device__ __forceinline__ unsigned smem_u32(const void* p) {
  unsigned a;
  asm("{ .reg .u64 t; cvta.to.shared.u64 t, %1; cvt.u32.u64 %0, t; }"
      : "=r"(a) : "l"(p));
  return a;
}
__device__ __forceinline__ void cp16(unsigned dst, const void* src) {
  asm volatile("cp.async.cg.shared.global [%0], [%1], 16;"
               :: "r"(dst), "l"(src));
}
__device__ __forceinline__ void mma_tf32(float* c, const unsigned* a,
                                         const unsigned* b) {
  asm volatile(
    "mma.sync.aligned.m16n8k8.row.col.f32.tf32.tf32.f32 "
    "{%0,%1,%2,%3}, {%4,%5,%6,%7}, {%8,%9}, {%0,%1,%2,%3};"
    : "+f"(c[0]), "+f"(c[1]), "+f"(c[2]), "+f"(c[3])
    : "r"(a[0]), "r"(a[1]), "r"(a[2]), "r"(a[3]), "r"(b[0]), "r"(b[1]));
}
// ldmatrix x4: loads 4 8x4-b32 matrices. Address = per-thread row ptr.
__device__ __forceinline__ void ldsm4(unsigned* r, unsigned addr) {
  asm volatile("ldmatrix.sync.aligned.m8n8.x4.shared.b16 {%0,%1,%2,%3}, [%4];"
    : "=r"(r[0]), "=r"(r[1]), "=r"(r[2]), "=r"(r[3]) : "r"(addr));
}

// ---------------------------------------------------------------------------
// Batched conversions (2 launches total)
// ---------------------------------------------------------------------------
// Elementwise tf32: x (8192 blk), cache_k (2048), cache_v (2048). 1024 el/blk.
__global__ __launch_bounds__(256)
void conv_all(const float* __restrict__ x, const float* __restrict__ ck,
              const float* __restrict__ cv, unsigned* __restrict__ xc,
              unsigned* __restrict__ ckc, unsigned* __restrict__ cvc) {
  int bid = blockIdx.x;
  const float* in; unsigned* out; size_t base;
  if (bid < 8192)       { in = x;  out = xc;  base = (size_t)bid * 1024; }
  else if (bid < 10240) { in = ck; out = ckc; base = (size_t)(bid - 8192) * 1024; }
  else                  { in = cv; out = cvc; base = (size_t)(bid - 10240) * 1024; }
  size_t i = base + threadIdx.x * 4;
  float4 v = *(const float4*)(in + i);
  uint4 o;
  o.x = f2tf(v.x); o.y = f2tf(v.y); o.z = f2tf(v.z); o.w = f2tf(v.w);
  *(uint4*)(out + i) = o;
}

// Transpose+tf32 for all 4 weights ([K][N] -> [N][K], K = DMODEL).
// Blocks: wq 16384 (128x128), wk 4096 (32x128), wv 4096, wo 16384.
__global__ __launch_bounds__(256)
void convT_all(const float* __restrict__ wq, const float* __restrict__ wk,
               const float* __restrict__ wv, const float* __restrict__ wo,
               unsigned* __restrict__ wqc, unsigned* __restrict__ wkc,
               unsigned* __restrict__ wvc, unsigned* __restrict__ woc) {
  __shared__ unsigned t[32][33];
  int bid = blockIdx.x;
  const float* in; unsigned* out; int N, bx, by;
  if (bid < 16384)      { in = wq; out = wqc; N = DMODEL;  bx = bid & 127; by = bid >> 7; }
  else if (bid < 20480) { int b = bid - 16384; in = wk; out = wkc; N = NHK * HD; bx = b & 31; by = b >> 5; }
  else if (bid < 24576) { int b = bid - 20480; in = wv; out = wvc; N = NHK * HD; bx = b & 31; by = b >> 5; }
  else                  { int b = bid - 24576; in = wo; out = woc; N = DMODEL;  bx = b & 127; by = b >> 7; }
  int n0 = bx * 32, k0 = by * 32;
  int tx = threadIdx.x & 31, ty = threadIdx.x >> 5;   // (32, 8)
  #pragma unroll
  for (int i = 0; i < 4; i++)
    t[ty + 8 * i][tx] = f2tf(in[(size_t)(k0 + ty + 8 * i) * N + n0 + tx]);
  __syncthreads();
  #pragma unroll
  for (int i = 0; i < 4; i++)
    out[(size_t)(n0 + ty + 8 * i) * DMODEL + k0 + tx] = t[tx][ty + 8 * i];
}

// ---------------------------------------------------------------------------
// Tensor-core GEMM: 128x128 CTA tile, BK=32, 3-stage cp.async, occ 2,
// ldmatrix fragment loads with register double-buffering over kk.
// ---------------------------------------------------------------------------
#define ASTRIDE 36
#define ABUF (128 * ASTRIDE)
#define BBUF (128 * ASTRIDE)
#define GEMM_SMEM ((3 * ABUF + 3 * BBUF) * 4)   // 110592 bytes

__device__ __forceinline__
void gemm_body(const unsigned* __restrict__ A, const unsigned* __restrict__ Bt,
               float* __restrict__ C, int N, int K,
               const float* __restrict__ rope, int bm, int bn, unsigned* gsm,
               bool cvt_out) {
  unsigned* AsB = gsm;                 // [3][128][36]
  unsigned* BsB = gsm + 3 * ABUF;      // [3][128][36]  ([n][k])
  int tid  = threadIdx.x;
  int wid  = tid >> 5, lane = tid & 31;
  int wm   = (wid >> 2) * 64;
  int wn   = (wid & 3) * 32;
  int gr   = lane >> 2;
  int tg   = lane & 3;
  int rsel = lane & 7, matid = lane >> 3;

  int arow = tid >> 1, acol = (tid & 1) * 16;

  auto issue_copy = [&](int k0, int buf) {
    unsigned adst = smem_u32(AsB + buf * ABUF + arow * ASTRIDE + acol);
    const unsigned* asrc = A + (size_t)(bm + arow) * K + k0 + acol;
    #pragma unroll
    for (int i = 0; i < 4; i++) cp16(adst + 16 * i, asrc + 4 * i);
    unsigned bdst = smem_u32(BsB + buf * BBUF + arow * ASTRIDE + acol);
    const unsigned* bsrc = Bt + (size_t)(bn + arow) * K + k0 + acol;
    #pragma unroll
    for (int i = 0; i < 4; i++) cp16(bdst + 16 * i, bsrc + 4 * i);
    asm volatile("cp.async.commit_group;" ::: "memory");
  };

  unsigned aA = smem_u32(AsB) +
      4 * ((wm + ((matid & 1) << 3) + rsel) * ASTRIDE + ((matid >> 1) << 2));
  unsigned bB = smem_u32(BsB) +
      4 * ((wn + ((matid >> 1) << 3) + rsel) * ASTRIDE + ((matid & 1) << 2));

  float acc[4][4][4] = {};
  int nit = K / 32;
  issue_copy(0, 0);
  issue_copy(32, 1);

  int buf = 0;
  for (int it = 0; it < nit; it++) {
    if (it < nit - 1)
      asm volatile("cp.async.wait_group 1;" ::: "memory");
    else
      asm volatile("cp.async.wait_group 0;" ::: "memory");
    __syncthreads();
    if (it + 2 < nit) issue_copy((it + 2) * 32, (it + 2) % 3);

    unsigned aAb = aA + buf * (ABUF * 4);
    unsigned bBb = bB + buf * (BBUF * 4);

    unsigned af[2][4][4], bf[2][2][4];
    #pragma unroll
    for (int mt = 0; mt < 4; mt++)
      ldsm4(af[0][mt], aAb + mt * (16 * ASTRIDE * 4));
    #pragma unroll
    for (int np = 0; np < 2; np++)
      ldsm4(bf[0][np], bBb + np * (16 * ASTRIDE * 4));

    #pragma unroll
    for (int k8 = 0; k8 < 4; k8++) {
      int cb = k8 & 1, nb = cb ^ 1;
      if (k8 < 3) {
        int kk = (k8 + 1) * 8;
        #pragma unroll
        for (int mt = 0; mt < 4; mt++)
          ldsm4(af[nb][mt], aAb + mt * (16 * ASTRIDE * 4) + kk * 4);
        #pragma unroll
        for (int np = 0; np < 2; np++)
          ldsm4(bf[nb][np], bBb + np * (16 * ASTRIDE * 4) + kk * 4);
      }
      #pragma unroll
      for (int mt = 0; mt < 4; mt++)
        #pragma unroll
        for (int nt = 0; nt < 4; nt++)
          mma_tf32(acc[mt][nt], af[cb][mt], &bf[cb][nt >> 1][(nt & 1) * 2]);
    }
    buf = (buf + 1) % 3;
  }

  #pragma unroll
  for (int mt = 0; mt < 4; mt++) {
    #pragma unroll
    for (int half = 0; half < 2; half++) {
      int m = bm + wm + mt * 16 + gr + half * 8;
      const float* rp = rope ? (rope + (size_t)m * HD) : (const float*)0;
      #pragma unroll
      for (int nt = 0; nt < 4; nt++) {
        int n = bn + wn + nt * 8 + 2 * tg;
        float x = acc[mt][nt][half * 2 + 0];
        float y = acc[mt][nt][half * 2 + 1];
        if (rp) {
          x *= rp[n & (HD - 1)];
          y *= rp[(n + 1) & (HD - 1)];
        }
        float2 v;
        if (cvt_out) {
          v.x = __uint_as_float(f2tf(x));
          v.y = __uint_as_float(f2tf(y));
        } else {
          v.x = x; v.y = y;
        }
        *(float2*)&C[(size_t)m * N + n] = v;
      }
    }
  }
}

// Fused QKV, packed grid: [0,512) Q (32nb x 16mb), [512,640) K, [640,768) V
__global__ __launch_bounds__(256, 2)
void gemm_qkv(const unsigned* __restrict__ x,
              const unsigned* __restrict__ wq, const unsigned* __restrict__ wk,
              const unsigned* __restrict__ wv,
              unsigned* __restrict__ q, unsigned* __restrict__ k,
              unsigned* __restrict__ v, const float* __restrict__ rope) {
  extern __shared__ unsigned gsm[];
  int bid = blockIdx.x;
  const unsigned* B; unsigned* C; int N; const float* rp; int bx, by;
  if (bid < 512) {
    B = wq; C = q; N = DMODEL; rp = rope;
    bx = bid & 31; by = bid >> 5;
  } else if (bid < 640) {
    int b2 = bid - 512;
    B = wk; C = k; N = NHK * HD; rp = rope;
    bx = b2 & 7; by = b2 >> 3;
  } else {
    int b2 = bid - 640;
    B = wv; C = v; N = NHK * HD; rp = (const float*)0;
    bx = b2 & 7; by = b2 >> 3;
  }
  gemm_body(x, B, (float*)C, N, DMODEL, rp, by * 128, bx * 128, gsm, true);
}

__global__ __launch_bounds__(256, 2)
void gemm_mma(const unsigned* __restrict__ A, const unsigned* __restrict__ Bt,
              float* __restrict__ C, int N, int K) {
  extern __shared__ unsigned gsm[];
  gemm_body(A, Bt, C, N, K, (const float*)0,
            blockIdx.y * 128, blockIdx.x * 128, gsm, false);
}

// ---------------------------------------------------------------------------
// Tensor-core flash attention, 256 threads, ldmatrix, GQA 2-heads/CTA,
// register double-buffered S-loop fragments (PV loop plain: reg budget).
// ---------------------------------------------------------------------------
#define BQ  128
#define BKV 64
#define AQS 0
#define AKS 16896
#define KBUF 8448
#define AVS 33792
#define APS 42496
#define AMS 51200
#define ALS 51328
#define AAS 51456
#define ASX 51584
#define ASS 51840
#define ATTN_SMEM_BYTES (52096 * 4)

__global__ __launch_bounds__(256, 1)
void attn_mma(const unsigned* __restrict__ Q, const unsigned* __restrict__ Kn,
              const unsigned* __restrict__ Vn, const unsigned* __restrict__ cK,
              const unsigned* __restrict__ cV, unsigned* __restrict__ Out) {
  extern __shared__ unsigned sm_u[];
  float* sm_f = reinterpret_cast<float*>(sm_u);
  unsigned* Qs  = sm_u + AQS;
  unsigned* KsA = sm_u + AKS;
  unsigned* Vs  = sm_u + AVS;
  unsigned* Pu  = sm_u + APS;
  float* m_s  = sm_f + AMS;
  float* l_s  = sm_f + ALS;
  float* al_s = sm_f + AAS;
  float* smax = sm_f + ASX;   // [2][128]
  float* ssum = sm_f + ASS;   // [2][128]

  int tid = threadIdx.x;
  int bid = blockIdx.x;
  int qt = 31 - (bid >> 4);             // heaviest q-tile first
  int sub = bid & 15;
  int hk = sub >> 1;
  int ha = hk * 4 + (sub & 1) * 2;      // first head of the pair
  int q0 = qt * 64;                     // 64-query range per head
  int wid = tid >> 5, lane = tid & 31;
  int gr = lane >> 2, tg = lane & 3;
  int wm = (wid >> 1) * 32;
  int wn = wid & 1;
  int rsel = lane & 7, matid = lane >> 3;
  const float scale = 0.08838834764831845f;

  unsigned sbase = smem_u32(sm_u);
  unsigned qA = sbase + 4 * (AQS +
      (wm + ((matid & 1) << 3) + rsel) * 132 + ((matid >> 1) << 2));
  unsigned kB = sbase + 4 * (AKS +
      (wn * 32 + ((matid >> 1) << 3) + rsel) * 132 + ((matid & 1) << 2));
  unsigned vB = sbase + 4 * (AVS +
      (wn * 64 + ((matid >> 1) << 3) + rsel) * 68 + ((matid & 1) << 2));
  unsigned pA = sbase + 4 * (APS +
      (wm + ((matid & 1) << 3) + rsel) * 68 + ((matid >> 1) << 2));

  // ---- load Q tile: rows 0-63 head ha, rows 64-127 head ha+1 ----
  #pragma unroll
  for (int i = 0; i < 16; i++) {
    int lin = tid + i * 256;
    int r = lin & 127, d16 = lin >> 7;
    int head = ha + (r >> 6);
    int qg = q0 + (r & 63);
    uint4 v = *(const uint4*)&Q[(size_t)qg * DMODEL + head * HD + d16 * 4];
    *(uint4*)&Qs[r * 132 + d16 * 4] = v;
  }
  if (tid < 128) { m_s[tid] = -1e30f; l_s[tid] = 0.0f; }

  // ---- load K tile 0 into Ks[0] (natural [t][132]) ----
  #pragma unroll
  for (int i = 0; i < 8; i++) {
    int lin = tid + i * 256;
    int t = lin >> 5, d16 = lin & 31;
    uint4 v = *(const uint4*)&cK[(size_t)t * (NHK * HD) + hk * HD + d16 * 4];
    *(uint4*)&KsA[t * 132 + d16 * 4] = v;
  }

  float o[2][8][4] = {};
  int ntiles = 33 + qt;
  int cur = 0;

  for (int tile = 0; tile < ntiles; tile++) {
    int t0 = tile * BKV;
    bool isnew = (t0 >= TCACHE);
    const unsigned* vb = isnew ? Vn : cV;
    int tr0 = t0 & (TCACHE - 1);
    __syncthreads();   // P/Vs free; stats final; Ks[cur^1] free

    // ---- prefetch V(tile) and K(tile+1) into registers ----
    uint4 vreg[8], kreg[8];
    #pragma unroll
    for (int i = 0; i < 8; i++) {
      int lin = tid + i * 256;
      int t = lin & 63, d4 = lin >> 6;
      vreg[i] = *(const uint4*)&vb[(size_t)(tr0 + t) * (NHK * HD) + hk * HD + d4 * 4];
    }
    bool havek = (tile + 1 < ntiles);
    if (havek) {
      int t1 = t0 + BKV;
      const unsigned* kb2 = (t1 >= TCACHE) ? Kn : cK;
      int tr1 = t1 & (TCACHE - 1);
      #pragma unroll
      for (int i = 0; i < 8; i++) {
        int lin = tid + i * 256;
        int t = lin >> 5, d16 = lin & 31;
        kreg[i] = *(const uint4*)&kb2[(size_t)(tr1 + t) * (NHK * HD) + hk * HD + d16 * 4];
      }
    }

    // ---- S = Q K^T : warp tile 32q x 32t (ldmatrix, reg double-buffered) ----
    float s[2][4][4] = {};
    unsigned kBb = kB + cur * (KBUF * 4);
    {
      unsigned af[2][2][4], bf[2][2][4];
      ldsm4(af[0][0], qA);
      ldsm4(af[0][1], qA + 16 * 132 * 4);
      ldsm4(bf[0][0], kBb);
      ldsm4(bf[0][1], kBb + 16 * 132 * 4);
      #pragma unroll
      for (int k8 = 0; k8 < 16; k8++) {
        int cb = k8 & 1, nb = cb ^ 1;
        if (k8 < 15) {
          int kk = (k8 + 1) * 8;
          ldsm4(af[nb][0], qA + kk * 4);
          ldsm4(af[nb][1], qA + 16 * 132 * 4 + kk * 4);
          ldsm4(bf[nb][0], kBb + kk * 4);
          ldsm4(bf[nb][1], kBb + 16 * 132 * 4 + kk * 4);
        }
        #pragma unroll
        for (int mt = 0; mt < 2; mt++)
          #pragma unroll
          for (int nt = 0; nt < 4; nt++)
            mma_tf32(s[mt][nt], af[cb][mt], &bf[cb][nt >> 1][(nt & 1) * 2]);
      }
    }

    // ---- store V tile ([d][t]) ----
    #pragma unroll
    for (int i = 0; i < 8; i++) {
      int lin = tid + i * 256;
      int t = lin & 63, d4 = lin >> 6;
      Vs[(d4 * 4 + 0) * 68 + t] = vreg[i].x;
      Vs[(d4 * 4 + 1) * 68 + t] = vreg[i].y;
      Vs[(d4 * 4 + 2) * 68 + t] = vreg[i].z;
      Vs[(d4 * 4 + 3) * 68 + t] = vreg[i].w;
    }

    // ---- scale + causal mask (row r -> query q0 + (r&63)) ----
    #pragma unroll
    for (int mt = 0; mt < 2; mt++)
      #pragma unroll
      for (int nt = 0; nt < 4; nt++) {
        int c0 = wn * 32 + nt * 8 + 2 * tg;
        #pragma unroll
        for (int half = 0; half < 2; half++) {
          int r = wm + mt * 16 + gr + half * 8;
          int qg = q0 + (r & 63);
          float x = s[mt][nt][half * 2 + 0] * scale;
          float y = s[mt][nt][half * 2 + 1] * scale;
          if (isnew) {
            if (t0 + c0     - TCACHE > qg) x = -1e30f;
            if (t0 + c0 + 1 - TCACHE > qg) y = -1e30f;
          }
          s[mt][nt][half * 2 + 0] = x;
          s[mt][nt][half * 2 + 1] = y;
        }
      }

    // ---- row max: local, shfl over tg, publish ----
    float pm[2][2], mold[2][2];
    #pragma unroll
    for (int mt = 0; mt < 2; mt++)
      #pragma unroll
      for (int hf = 0; hf < 2; hf++) {
        float m1 = -1e30f;
        #pragma unroll
        for (int nt = 0; nt < 4; nt++)
          m1 = fmaxf(m1, fmaxf(s[mt][nt][hf * 2], s[mt][nt][hf * 2 + 1]));
        pm[mt][hf] = m1;
      }
    #pragma unroll
    for (int mt = 0; mt < 2; mt++)
      #pragma unroll
      for (int hf = 0; hf < 2; hf++) {
        pm[mt][hf] = fmaxf(pm[mt][hf], __shfl_xor_sync(0xffffffffu, pm[mt][hf], 1));
        pm[mt][hf] = fmaxf(pm[mt][hf], __shfl_xor_sync(0xffffffffu, pm[mt][hf], 2));
        int row = wm + mt * 16 + hf * 8 + gr;
        mold[mt][hf] = m_s[row];
        if (tg == 0) smax[wn * 128 + row] = pm[mt][hf];
      }
    __syncthreads();   // smax ready; Vs complete

    // ---- exp in registers, P as tf32, partial sums ----
    float al[2][2], mn[2][2], ps[2][2];
    #pragma unroll
    for (int mt = 0; mt < 2; mt++)
      #pragma unroll
      for (int hf = 0; hf < 2; hf++) {
        int row = wm + mt * 16 + hf * 8 + gr;
        float mnew = fmaxf(mold[mt][hf],
                           fmaxf(smax[row], smax[128 + row]));
        mn[mt][hf] = mnew;
        al[mt][hf] = __expf(mold[mt][hf] - mnew);
        float sum = 0.0f;
        #pragma unroll
        for (int nt = 0; nt < 4; nt++) {
          int c0 = wn * 32 + nt * 8 + 2 * tg;
          float p0 = __expf(s[mt][nt][hf * 2 + 0] - mnew);
          float p1 = __expf(s[mt][nt][hf * 2 + 1] - mnew);
          sum += p0 + p1;
          uint2 w; w.x = f2tf(p0); w.y = f2tf(p1);
          *(uint2*)&Pu[row * 68 + c0] = w;
        }
        ps[mt][hf] = sum;
      }
    #pragma unroll
    for (int mt = 0; mt < 2; mt++)
      #pragma unroll
      for (int hf = 0; hf < 2; hf++) {
        ps[mt][hf] += __shfl_xor_sync(0xffffffffu, ps[mt][hf], 1);
        ps[mt][hf] += __shfl_xor_sync(0xffffffffu, ps[mt][hf], 2);
        int row = wm + mt * 16 + hf * 8 + gr;
        if (tg == 0) {
          ssum[wn * 128 + row] = ps[mt][hf];
          if (wn == 0) { al_s[row] = al[mt][hf]; m_s[row] = mn[mt][hf]; }
        }
      }

    // ---- store K(tile+1) into Ks[cur^1] ----
    if (havek) {
      unsigned* Kx = KsA + (cur ^ 1) * KBUF;
      #pragma unroll
      for (int i = 0; i < 8; i++) {
        int lin = tid + i * 256;
        int t = lin >> 5, d16 = lin & 31;
        *(uint4*)&Kx[t * 132 + d16 * 4] = kreg[i];
      }
    }
    __syncthreads();   // P, ssum, alpha, next K ready

    // ---- l update (one lane per row) ----
    if (wn == 0 && tg == 0) {
      #pragma unroll
      for (int mt = 0; mt < 2; mt++)
        #pragma unroll
        for (int hf = 0; hf < 2; hf++) {
          int row = wm + mt * 16 + hf * 8 + gr;
          l_s[row] = l_s[row] * al[mt][hf] + ssum[row] + ssum[128 + row];
        }
    }

    // ---- rescale O by alpha, then O += P V (ldmatrix, plain loop) ----
    float alv[2][2];
    alv[0][0] = al_s[wm + gr];
    alv[0][1] = al_s[wm + 8 + gr];
    alv[1][0] = al_s[wm + 16 + gr];
    alv[1][1] = al_s[wm + 24 + gr];
    #pragma unroll
    for (int mt = 0; mt < 2; mt++)
      #pragma unroll
      for (int nt = 0; nt < 8; nt++) {
        o[mt][nt][0] *= alv[mt][0];
        o[mt][nt][1] *= alv[mt][0];
        o[mt][nt][2] *= alv[mt][1];
        o[mt][nt][3] *= alv[mt][1];
      }
    #pragma unroll
    for (int k8 = 0; k8 < 8; k8++) {
      int kk = k8 * 8;
      unsigned af[2][4], bf[4][4];
      ldsm4(af[0], pA + kk * 4);
      ldsm4(af[1], pA + 16 * 68 * 4 + kk * 4);
      #pragma unroll
      for (int np = 0; np < 4; np++)
        ldsm4(bf[np], vB + np * (16 * 68 * 4) + kk * 4);
      #pragma unroll
      for (int mt = 0; mt < 2; mt++)
        #pragma unroll
        for (int nt = 0; nt < 8; nt++)
          mma_tf32(o[mt][nt], af[mt], &bf[nt >> 1][(nt & 1) * 2]);
    }
    cur ^= 1;
  }
  __syncthreads();   // final l_s visible

  // ---- epilogue: O /= l, write tf32 bits (row r -> head ha+(r>>6)) ----
  float inv[2][2];
  inv[0][0] = 1.0f / l_s[wm + gr];
  inv[0][1] = 1.0f / l_s[wm + 8 + gr];
  inv[1][0] = 1.0f / l_s[wm + 16 + gr];
  inv[1][1] = 1.0f / l_s[wm + 24 + gr];
  #pragma unroll
  for (int mt = 0; mt < 2; mt++)
    #pragma unroll
    for (int half = 0; half < 2; half++) {
      int r = wm + mt * 16 + gr + half * 8;
      int head = ha + (r >> 6);
      int qg = q0 + (r & 63);
      #pragma unroll
      for (int nt = 0; nt < 8; nt++) {
        int c = wn * 64 + nt * 8 + 2 * tg;
        uint2 w;
        w.x = f2tf(o[mt][nt][half * 2 + 0] * inv[mt][half]);
        w.y = f2tf(o[mt][nt][half * 2 + 1] * inv[mt][half]);
        *(uint2*)&Out[(size_t)qg * DMODEL + head * HD + c] = w;
      }
    }
}

// ---------------------------------------------------------------------------
// Launch
// ---------------------------------------------------------------------------
extern "C" void kernel_launch(void* const* d_in, const int* in_sizes, int n_in,
                              void* d_out, int out_size) {
  const float* x       = (const float*)d_in[0];
  const float* rope    = (const float*)d_in[1];
  // d_in[2] = mask: unused (causality implemented exactly in-kernel)
  const float* cache_k = (const float*)d_in[3];
  const float* cache_v = (const float*)d_in[4];
  const float* wq      = (const float*)d_in[5];
  const float* wk      = (const float*)d_in[6];
  const float* wv      = (const float*)d_in[7];
  const float* wo      = (const float*)d_in[8];
  float* out = (float*)d_out;

  unsigned *q, *k, *v, *ao, *xc, *wqc, *wkc, *wvc, *woc, *ckc, *cvc;
  cudaGetSymbolAddress((void**)&q,   g_q);
  cudaGetSymbolAddress((void**)&k,   g_k);
  cudaGetSymbolAddress((void**)&v,   g_v);
  cudaGetSymbolAddress((void**)&ao,  g_ao);
  cudaGetSymbolAddress((void**)&xc,  g_xc);
  cudaGetSymbolAddress((void**)&wqc, g_wqc);
  cudaGetSymbolAddress((void**)&wkc, g_wkc);
  cudaGetSymbolAddress((void**)&wvc, g_wvc);
  cudaGetSymbolAddress((void**)&woc, g_woc);
  cudaGetSymbolAddress((void**)&ckc, g_ckc);
  cudaGetSymbolAddress((void**)&cvc, g_cvc);

  cudaFuncSetAttribute(gemm_qkv, cudaFuncAttributeMaxDynamicSharedMemorySize,
                       GEMM_SMEM);
  cudaFuncSetAttribute(gemm_mma, cudaFuncAttributeMaxDynamicSharedMemorySize,
                       GEMM_SMEM);
  cudaFuncSetAttribute(attn_mma, cudaFuncAttributeMaxDynamicSharedMemorySize,
                       ATTN_SMEM_BYTES);

  // Batched conversions (2 launches)
  conv_all<<<12288, 256>>>(x, cache_k, cache_v, xc, ckc, cvc);
  convT_all<<<40960, 256>>>(wq, wk, wv, wo, wqc, wkc, wvc, woc);

  // Fused QKV projection (packed: 512 Q + 128 K + 128 V)
  gemm_qkv<<<768, 256, GEMM_SMEM>>>(xc, wqc, wkc, wvc, q, k, v, rope);

  // Flash attention (GQA 2-heads/CTA, heaviest q-tiles first)
  attn_mma<<<512, 256, ATTN_SMEM_BYTES>>>(q, k, v, ckc, cvc, ao);

  // Output projection
  gemm_mma<<<dim3(DMODEL / 128, S_LEN / 128), 256, GEMM_SMEM>>>(
      ao, woc, out, DMODEL, DMODEL);
}

// round 17
// speedup vs baseline: 1.5564x; 1.0092x over previous
#include <cuda_runtime.h>
#include <cuda_bf16.h>

// Problem constants
#define S_LEN  2048
#define DMODEL 4096
#define NH     32
#define NHK    8
#define HD     128
#define TCACHE 2048

// ---------------------------------------------------------------------------
// Scratch (allocation-free). q/k/v/ao hold tf32 bits. Weights stored
// TRANSPOSED [N][K] (for [n][k] smem layout feeding ldmatrix B-fragments).
// ---------------------------------------------------------------------------
__device__ unsigned g_q [S_LEN * DMODEL];
__device__ unsigned g_k [S_LEN * NHK * HD];
__device__ unsigned g_v [S_LEN * NHK * HD];
__device__ unsigned g_ao[S_LEN * DMODEL];
__device__ unsigned g_xc [S_LEN * DMODEL];
__device__ unsigned g_wqc[DMODEL * DMODEL];      // [N=4096][K=4096]
__device__ unsigned g_wkc[NHK * HD * DMODEL];    // [N=1024][K=4096]
__device__ unsigned g_wvc[NHK * HD * DMODEL];
__device__ unsigned g_woc[DMODEL * DMODEL];
__device__ unsigned g_ckc[TCACHE * NHK * HD];
__device__ unsigned g_cvc[TCACHE * NHK * HD];

// ---------------------------------------------------------------------------
// Helpers
// ---------------------------------------------------------------------------
__device__ __forceinline__ unsigned f2tf(float f) {
  unsigned u;
  asm("cvt.rn.tf32.f32 %0, %1;" : "=r"(u) : "f"(f));
  return u;
}
__device__ __forceinline__ unsigned smem_u32(const void* p) {
  unsigned a;
  asm("{ .reg .u64 t; cvta.to.shared.u64 t, %1; cvt.u32.u64 %0, t; }"
      : "=r"(a) : "l"(p));
  return a;
}
__device__ __forceinline__ void cp16(unsigned dst, const void* src) {
  asm volatile("cp.async.cg.shared.global [%0], [%1], 16;"
               :: "r"(dst), "l"(src));
}
__device__ __forceinline__ void mma_tf32(float* c, const unsigned* a,
                                         const unsigned* b) {
  asm volatile(
    "mma.sync.aligned.m16n8k8.row.col.f32.tf32.tf32.f32 "
    "{%0,%1,%2,%3}, {%4,%5,%6,%7}, {%8,%9}, {%0,%1,%2,%3};"
    : "+f"(c[0]), "+f"(c[1]), "+f"(c[2]), "+f"(c[3])
    : "r"(a[0]), "r"(a[1]), "r"(a[2]), "r"(a[3]), "r"(b[0]), "r"(b[1]));
}
// ldmatrix x4: loads 4 8x4-b32 matrices. Address = per-thread row ptr.
__device__ __forceinline__ void ldsm4(unsigned* r, unsigned addr) {
  asm volatile("ldmatrix.sync.aligned.m8n8.x4.shared.b16 {%0,%1,%2,%3}, [%4];"
    : "=r"(r[0]), "=r"(r[1]), "=r"(r[2]), "=r"(r[3]) : "r"(addr));
}

// ---------------------------------------------------------------------------
// Batched conversions (2 launches total)
// ---------------------------------------------------------------------------
__global__ __launch_bounds__(256)
void conv_all(const float* __restrict__ x, const float* __restrict__ ck,
              const float* __restrict__ cv, unsigned* __restrict__ xc,
              unsigned* __restrict__ ckc, unsigned* __restrict__ cvc) {
  int bid = blockIdx.x;
  const float* in; unsigned* out; size_t base;
  if (bid < 8192)       { in = x;  out = xc;  base = (size_t)bid * 1024; }
  else if (bid < 10240) { in = ck; out = ckc; base = (size_t)(bid - 8192) * 1024; }
  else                  { in = cv; out = cvc; base = (size_t)(bid - 10240) * 1024; }
  size_t i = base + threadIdx.x * 4;
  float4 v = *(const float4*)(in + i);
  uint4 o;
  o.x = f2tf(v.x); o.y = f2tf(v.y); o.z = f2tf(v.z); o.w = f2tf(v.w);
  *(uint4*)(out + i) = o;
}

__global__ __launch_bounds__(256)
void convT_all(const float* __restrict__ wq, const float* __restrict__ wk,
               const float* __restrict__ wv, const float* __restrict__ wo,
               unsigned* __restrict__ wqc, unsigned* __restrict__ wkc,
               unsigned* __restrict__ wvc, unsigned* __restrict__ woc) {
  __shared__ unsigned t[32][33];
  int bid = blockIdx.x;
  const float* in; unsigned* out; int N, bx, by;
  if (bid < 16384)      { in = wq; out = wqc; N = DMODEL;  bx = bid & 127; by = bid >> 7; }
  else if (bid < 20480) { int b = bid - 16384; in = wk; out = wkc; N = NHK * HD; bx = b & 31; by = b >> 5; }
  else if (bid < 24576) { int b = bid - 20480; in = wv; out = wvc; N = NHK * HD; bx = b & 31; by = b >> 5; }
  else                  { int b = bid - 24576; in = wo; out = woc; N = DMODEL;  bx = b & 127; by = b >> 7; }
  int n0 = bx * 32, k0 = by * 32;
  int tx = threadIdx.x & 31, ty = threadIdx.x >> 5;   // (32, 8)
  #pragma unroll
  for (int i = 0; i < 4; i++)
    t[ty + 8 * i][tx] = f2tf(in[(size_t)(k0 + ty + 8 * i) * N + n0 + tx]);
  __syncthreads();
  #pragma unroll
  for (int i = 0; i < 4; i++)
    out[(size_t)(n0 + ty + 8 * i) * DMODEL + k0 + tx] = t[tx][ty + 8 * i];
}

// ---------------------------------------------------------------------------
// Tensor-core GEMM: 128x128 CTA tile, BK=32, 3-stage cp.async, occ 2,
// ldmatrix fragment loads with register double-buffering over kk.
// (unchanged from round 15 — proven)
// ---------------------------------------------------------------------------
#define ASTRIDE 36
#define ABUF (128 * ASTRIDE)
#define BBUF (128 * ASTRIDE)
#define GEMM_SMEM ((3 * ABUF + 3 * BBUF) * 4)   // 110592 bytes

__device__ __forceinline__
void gemm_body(const unsigned* __restrict__ A, const unsigned* __restrict__ Bt,
               float* __restrict__ C, int N, int K,
               const float* __restrict__ rope, int bm, int bn, unsigned* gsm,
               bool cvt_out) {
  unsigned* AsB = gsm;                 // [3][128][36]
  unsigned* BsB = gsm + 3 * ABUF;      // [3][128][36]  ([n][k])
  int tid  = threadIdx.x;
  int wid  = tid >> 5, lane = tid & 31;
  int wm   = (wid >> 2) * 64;
  int wn   = (wid & 3) * 32;
  int gr   = lane >> 2;
  int tg   = lane & 3;
  int rsel = lane & 7, matid = lane >> 3;

  int arow = tid >> 1, acol = (tid & 1) * 16;

  auto issue_copy = [&](int k0, int buf) {
    unsigned adst = smem_u32(AsB + buf * ABUF + arow * ASTRIDE + acol);
    const unsigned* asrc = A + (size_t)(bm + arow) * K + k0 + acol;
    #pragma unroll
    for (int i = 0; i < 4; i++) cp16(adst + 16 * i, asrc + 4 * i);
    unsigned bdst = smem_u32(BsB + buf * BBUF + arow * ASTRIDE + acol);
    const unsigned* bsrc = Bt + (size_t)(bn + arow) * K + k0 + acol;
    #pragma unroll
    for (int i = 0; i < 4; i++) cp16(bdst + 16 * i, bsrc + 4 * i);
    asm volatile("cp.async.commit_group;" ::: "memory");
  };

  unsigned aA = smem_u32(AsB) +
      4 * ((wm + ((matid & 1) << 3) + rsel) * ASTRIDE + ((matid >> 1) << 2));
  unsigned bB = smem_u32(BsB) +
      4 * ((wn + ((matid >> 1) << 3) + rsel) * ASTRIDE + ((matid & 1) << 2));

  float acc[4][4][4] = {};
  int nit = K / 32;
  issue_copy(0, 0);
  issue_copy(32, 1);

  int buf = 0;
  for (int it = 0; it < nit; it++) {
    if (it < nit - 1)
      asm volatile("cp.async.wait_group 1;" ::: "memory");
    else
      asm volatile("cp.async.wait_group 0;" ::: "memory");
    __syncthreads();
    if (it + 2 < nit) issue_copy((it + 2) * 32, (it + 2) % 3);

    unsigned aAb = aA + buf * (ABUF * 4);
    unsigned bBb = bB + buf * (BBUF * 4);

    unsigned af[2][4][4], bf[2][2][4];
    #pragma unroll
    for (int mt = 0; mt < 4; mt++)
      ldsm4(af[0][mt], aAb + mt * (16 * ASTRIDE * 4));
    #pragma unroll
    for (int np = 0; np < 2; np++)
      ldsm4(bf[0][np], bBb + np * (16 * ASTRIDE * 4));

    #pragma unroll
    for (int k8 = 0; k8 < 4; k8++) {
      int cb = k8 & 1, nb = cb ^ 1;
      if (k8 < 3) {
        int kk = (k8 + 1) * 8;
        #pragma unroll
        for (int mt = 0; mt < 4; mt++)
          ldsm4(af[nb][mt], aAb + mt * (16 * ASTRIDE * 4) + kk * 4);
        #pragma unroll
        for (int np = 0; np < 2; np++)
          ldsm4(bf[nb][np], bBb + np * (16 * ASTRIDE * 4) + kk * 4);
      }
      #pragma unroll
      for (int mt = 0; mt < 4; mt++)
        #pragma unroll
        for (int nt = 0; nt < 4; nt++)
          mma_tf32(acc[mt][nt], af[cb][mt], &bf[cb][nt >> 1][(nt & 1) * 2]);
    }
    buf = (buf + 1) % 3;
  }

  #pragma unroll
  for (int mt = 0; mt < 4; mt++) {
    #pragma unroll
    for (int half = 0; half < 2; half++) {
      int m = bm + wm + mt * 16 + gr + half * 8;
      const float* rp = rope ? (rope + (size_t)m * HD) : (const float*)0;
      #pragma unroll
      for (int nt = 0; nt < 4; nt++) {
        int n = bn + wn + nt * 8 + 2 * tg;
        float x = acc[mt][nt][half * 2 + 0];
        float y = acc[mt][nt][half * 2 + 1];
        if (rp) {
          x *= rp[n & (HD - 1)];
          y *= rp[(n + 1) & (HD - 1)];
        }
        float2 v;
        if (cvt_out) {
          v.x = __uint_as_float(f2tf(x));
          v.y = __uint_as_float(f2tf(y));
        } else {
          v.x = x; v.y = y;
        }
        *(float2*)&C[(size_t)m * N + n] = v;
      }
    }
  }
}

// Fused QKV, packed grid: [0,512) Q (32nb x 16mb), [512,640) K, [640,768) V
__global__ __launch_bounds__(256, 2)
void gemm_qkv(const unsigned* __restrict__ x,
              const unsigned* __restrict__ wq, const unsigned* __restrict__ wk,
              const unsigned* __restrict__ wv,
              unsigned* __restrict__ q, unsigned* __restrict__ k,
              unsigned* __restrict__ v, const float* __restrict__ rope) {
  extern __shared__ unsigned gsm[];
  int bid = blockIdx.x;
  const unsigned* B; unsigned* C; int N; const float* rp; int bx, by;
  if (bid < 512) {
    B = wq; C = q; N = DMODEL; rp = rope;
    bx = bid & 31; by = bid >> 5;
  } else if (bid < 640) {
    int b2 = bid - 512;
    B = wk; C = k; N = NHK * HD; rp = rope;
    bx = b2 & 7; by = b2 >> 3;
  } else {
    int b2 = bid - 640;
    B = wv; C = v; N = NHK * HD; rp = (const float*)0;
    bx = b2 & 7; by = b2 >> 3;
  }
  gemm_body(x, B, (float*)C, N, DMODEL, rp, by * 128, bx * 128, gsm, true);
}

__global__ __launch_bounds__(256, 2)
void gemm_mma(const unsigned* __restrict__ A, const unsigned* __restrict__ Bt,
              float* __restrict__ C, int N, int K) {
  extern __shared__ unsigned gsm[];
  gemm_body(A, Bt, C, N, K, (const float*)0,
            blockIdx.y * 128, blockIdx.x * 128, gsm, false);
}

// ---------------------------------------------------------------------------
// Tensor-core flash attention, 256 threads, ldmatrix, GQA 2-heads/CTA,
// register double-buffered S-loop fragments, cp.async K staging (frees the
// kreg prefetch registers and removes the post-softmax K store phase).
// ---------------------------------------------------------------------------
#define BQ  128
#define BKV 64
#define AQS 0
#define AKS 16896
#define KBUF 8448
#define AVS 33792
#define APS 42496
#define AMS 51200
#define ALS 51328
#define AAS 51456
#define ASX 51584
#define ASS 51840
#define ATTN_SMEM_BYTES (52096 * 4)

__global__ __launch_bounds__(256, 1)
void attn_mma(const unsigned* __restrict__ Q, const unsigned* __restrict__ Kn,
              const unsigned* __restrict__ Vn, const unsigned* __restrict__ cK,
              const unsigned* __restrict__ cV, unsigned* __restrict__ Out) {
  extern __shared__ unsigned sm_u[];
  float* sm_f = reinterpret_cast<float*>(sm_u);
  unsigned* Qs  = sm_u + AQS;
  unsigned* KsA = sm_u + AKS;
  unsigned* Vs  = sm_u + AVS;
  unsigned* Pu  = sm_u + APS;
  float* m_s  = sm_f + AMS;
  float* l_s  = sm_f + ALS;
  float* al_s = sm_f + AAS;
  float* smax = sm_f + ASX;   // [2][128]
  float* ssum = sm_f + ASS;   // [2][128]

  int tid = threadIdx.x;
  int bid = blockIdx.x;
  int qt = 31 - (bid >> 4);             // heaviest q-tile first
  int sub = bid & 15;
  int hk = sub >> 1;
  int ha = hk * 4 + (sub & 1) * 2;      // first head of the pair
  int q0 = qt * 64;                     // 64-query range per head
  int wid = tid >> 5, lane = tid & 31;
  int gr = lane >> 2, tg = lane & 3;
  int wm = (wid >> 1) * 32;
  int wn = wid & 1;
  int rsel = lane & 7, matid = lane >> 3;
  const float scale = 0.08838834764831845f;

  unsigned sbase = smem_u32(sm_u);
  unsigned qA = sbase + 4 * (AQS +
      (wm + ((matid & 1) << 3) + rsel) * 132 + ((matid >> 1) << 2));
  unsigned kB = sbase + 4 * (AKS +
      (wn * 32 + ((matid >> 1) << 3) + rsel) * 132 + ((matid & 1) << 2));
  unsigned vB = sbase + 4 * (AVS +
      (wn * 64 + ((matid >> 1) << 3) + rsel) * 68 + ((matid & 1) << 2));
  unsigned pA = sbase + 4 * (APS +
      (wm + ((matid & 1) << 3) + rsel) * 68 + ((matid >> 1) << 2));

  // K staging geometry (shared by prologue load and cp.async refills):
  // per thread 8 rows-of-16B: lin = tid + i*256; t = lin>>5, d16 = lin&31.
  int kst = tid >> 5;                   // base t row (stride 8 per i)
  int ksd = tid & 31;                   // 16B column

  // ---- load Q tile: rows 0-63 head ha, rows 64-127 head ha+1 ----
  #pragma unroll
  for (int i = 0; i < 16; i++) {
    int lin = tid + i * 256;
    int r = lin & 127, d16 = lin >> 7;
    int head = ha + (r >> 6);
    int qg = q0 + (r & 63);
    uint4 v = *(const uint4*)&Q[(size_t)qg * DMODEL + head * HD + d16 * 4];
    *(uint4*)&Qs[r * 132 + d16 * 4] = v;
  }
  if (tid < 128) { m_s[tid] = -1e30f; l_s[tid] = 0.0f; }

  // ---- load K tile 0 into Ks[0] (natural [t][132]) ----
  #pragma unroll
  for (int i = 0; i < 8; i++) {
    int t = kst + i * 8;
    uint4 v = *(const uint4*)&cK[(size_t)t * (NHK * HD) + hk * HD + ksd * 4];
    *(uint4*)&KsA[t * 132 + ksd * 4] = v;
  }

  float o[2][8][4] = {};
  int ntiles = 33 + qt;
  int cur = 0;

  for (int tile = 0; tile < ntiles; tile++) {
    int t0 = tile * BKV;
    bool isnew = (t0 >= TCACHE);
    const unsigned* vb = isnew ? Vn : cV;
    int tr0 = t0 & (TCACHE - 1);
    // Wait for this tile's K cp.async (issued last iteration), then sync:
    // makes all threads' Ks[cur] writes visible; P/Vs also free after this.
    asm volatile("cp.async.wait_group 0;" ::: "memory");
    __syncthreads();

    // ---- issue cp.async for K(tile+1) into Ks[cur^1] (buffer free now) ----
    bool havek = (tile + 1 < ntiles);
    if (havek) {
      int t1 = t0 + BKV;
      const unsigned* kb2 = (t1 >= TCACHE) ? Kn : cK;
      int tr1 = t1 & (TCACHE - 1);
      unsigned kdst = sbase + 4 * (AKS + (cur ^ 1) * KBUF);
      #pragma unroll
      for (int i = 0; i < 8; i++) {
        int t = kst + i * 8;
        cp16(kdst + 4 * (t * 132 + ksd * 4),
             &kb2[(size_t)(tr1 + t) * (NHK * HD) + hk * HD + ksd * 4]);
      }
      asm volatile("cp.async.commit_group;" ::: "memory");
    }

    // ---- prefetch V(tile) into registers ----
    uint4 vreg[8];
    #pragma unroll
    for (int i = 0; i < 8; i++) {
      int lin = tid + i * 256;
      int t = lin & 63, d4 = lin >> 6;
      vreg[i] = *(const uint4*)&vb[(size_t)(tr0 + t) * (NHK * HD) + hk * HD + d4 * 4];
    }

    // ---- S = Q K^T : warp tile 32q x 32t (ldmatrix, reg double-buffered) ----
    float s[2][4][4] = {};
    unsigned kBb = kB + cur * (KBUF * 4);
    {
      unsigned af[2][2][4], bf[2][2][4];
      ldsm4(af[0][0], qA);
      ldsm4(af[0][1], qA + 16 * 132 * 4);
      ldsm4(bf[0][0], kBb);
      ldsm4(bf[0][1], kBb + 16 * 132 * 4);
      #pragma unroll
      for (int k8 = 0; k8 < 16; k8++) {
        int cb = k8 & 1, nb = cb ^ 1;
        if (k8 < 15) {
          int kk = (k8 + 1) * 8;
          ldsm4(af[nb][0], qA + kk * 4);
          ldsm4(af[nb][1], qA + 16 * 132 * 4 + kk * 4);
          ldsm4(bf[nb][0], kBb + kk * 4);
          ldsm4(bf[nb][1], kBb + 16 * 132 * 4 + kk * 4);
        }
        #pragma unroll
        for (int mt = 0; mt < 2; mt++)
          #pragma unroll
          for (int nt = 0; nt < 4; nt++)
            mma_tf32(s[mt][nt], af[cb][mt], &bf[cb][nt >> 1][(nt & 1) * 2]);
      }
    }

    // ---- store V tile ([d][t]) ----
    #pragma unroll
    for (int i = 0; i < 8; i++) {
      int lin = tid + i * 256;
      int t = lin & 63, d4 = lin >> 6;
      Vs[(d4 * 4 + 0) * 68 + t] = vreg[i].x;
      Vs[(d4 * 4 + 1) * 68 + t] = vreg[i].y;
      Vs[(d4 * 4 + 2) * 68 + t] = vreg[i].z;
      Vs[(d4 * 4 + 3) * 68 + t] = vreg[i].w;
    }

    // ---- scale + causal mask (row r -> query q0 + (r&63)) ----
    #pragma unroll
    for (int mt = 0; mt < 2; mt++)
      #pragma unroll
      for (int nt = 0; nt < 4; nt++) {
        int c0 = wn * 32 + nt * 8 + 2 * tg;
        #pragma unroll
        for (int half = 0; half < 2; half++) {
          int r = wm + mt * 16 + gr + half * 8;
          int qg = q0 + (r & 63);
          float x = s[mt][nt][half * 2 + 0] * scale;
          float y = s[mt][nt][half * 2 + 1] * scale;
          if (isnew) {
            if (t0 + c0     - TCACHE > qg) x = -1e30f;
            if (t0 + c0 + 1 - TCACHE > qg) y = -1e30f;
          }
          s[mt][nt][half * 2 + 0] = x;
          s[mt][nt][half * 2 + 1] = y;
        }
      }

    // ---- row max: local, shfl over tg, publish ----
    float pm[2][2], mold[2][2];
    #pragma unroll
    for (int mt = 0; mt < 2; mt++)
      #pragma unroll
      for (int hf = 0; hf < 2; hf++) {
        float m1 = -1e30f;
        #pragma unroll
        for (int nt = 0; nt < 4; nt++)
          m1 = fmaxf(m1, fmaxf(s[mt][nt][hf * 2], s[mt][nt][hf * 2 + 1]));
        pm[mt][hf] = m1;
      }
    #pragma unroll
    for (int mt = 0; mt < 2; mt++)
      #pragma unroll
      for (int hf = 0; hf < 2; hf++) {
        pm[mt][hf] = fmaxf(pm[mt][hf], __shfl_xor_sync(0xffffffffu, pm[mt][hf], 1));
        pm[mt][hf] = fmaxf(pm[mt][hf], __shfl_xor_sync(0xffffffffu, pm[mt][hf], 2));
        int row = wm + mt * 16 + hf * 8 + gr;
        mold[mt][hf] = m_s[row];
        if (tg == 0) smax[wn * 128 + row] = pm[mt][hf];
      }
    __syncthreads();   // smax ready; Vs complete

    // ---- exp in registers, P as tf32, partial sums ----
    float al[2][2], mn[2][2], ps[2][2];
    #pragma unroll
    for (int mt = 0; mt < 2; mt++)
      #pragma unroll
      for (int hf = 0; hf < 2; hf++) {
        int row = wm + mt * 16 + hf * 8 + gr;
        float mnew = fmaxf(mold[mt][hf],
                           fmaxf(smax[row], smax[128 + row]));
        mn[mt][hf] = mnew;
        al[mt][hf] = __expf(mold[mt][hf] - mnew);
        float sum = 0.0f;
        #pragma unroll
        for (int nt = 0; nt < 4; nt++) {
          int c0 = wn * 32 + nt * 8 + 2 * tg;
          float p0 = __expf(s[mt][nt][hf * 2 + 0] - mnew);
          float p1 = __expf(s[mt][nt][hf * 2 + 1] - mnew);
          sum += p0 + p1;
          uint2 w; w.x = f2tf(p0); w.y = f2tf(p1);
          *(uint2*)&Pu[row * 68 + c0] = w;
        }
        ps[mt][hf] = sum;
      }
    #pragma unroll
    for (int mt = 0; mt < 2; mt++)
      #pragma unroll
      for (int hf = 0; hf < 2; hf++) {
        ps[mt][hf] += __shfl_xor_sync(0xffffffffu, ps[mt][hf], 1);
        ps[mt][hf] += __shfl_xor_sync(0xffffffffu, ps[mt][hf], 2);
        int row = wm + mt * 16 + hf * 8 + gr;
        if (tg == 0) {
          ssum[wn * 128 + row] = ps[mt][hf];
          if (wn == 0) { al_s[row] = al[mt][hf]; m_s[row] = mn[mt][hf]; }
        }
      }
    __syncthreads();   // P, ssum, alpha ready

    // ---- l update (one lane per row) ----
    if (wn == 0 && tg == 0) {
      #pragma unroll
      for (int mt = 0; mt < 2; mt++)
        #pragma unroll
        for (int hf = 0; hf < 2; hf++) {
          int row = wm + mt * 16 + hf * 8 + gr;
          l_s[row] = l_s[row] * al[mt][hf] + ssum[row] + ssum[128 + row];
        }
    }

    // ---- rescale O by alpha, then O += P V (ldmatrix, plain loop) ----
    float alv[2][2];
    alv[0][0] = al_s[wm + gr];
    alv[0][1] = al_s[wm + 8 + gr];
    alv[1][0] = al_s[wm + 16 + gr];
    alv[1][1] = al_s[wm + 24 + gr];
    #pragma unroll
    for (int mt = 0; mt < 2; mt++)
      #pragma unroll
      for (int nt = 0; nt < 8; nt++) {
        o[mt][nt][0] *= alv[mt][0];
        o[mt][nt][1] *= alv[mt][0];
        o[mt][nt][2] *= alv[mt][1];
        o[mt][nt][3] *= alv[mt][1];
      }
    #pragma unroll
    for (int k8 = 0; k8 < 8; k8++) {
      int kk = k8 * 8;
      unsigned af[2][4], bf[4][4];
      ldsm4(af[0], pA + kk * 4);
      ldsm4(af[1], pA + 16 * 68 * 4 + kk * 4);
      #pragma unroll
      for (int np = 0; np < 4; np++)
        ldsm4(bf[np], vB + np * (16 * 68 * 4) + kk * 4);
      #pragma unroll
      for (int mt = 0; mt < 2; mt++)
        #pragma unroll
        for (int nt = 0; nt < 8; nt++)
          mma_tf32(o[mt][nt], af[mt], &bf[nt >> 1][(nt & 1) * 2]);
    }
    cur ^= 1;
  }
  __syncthreads();   // final l_s visible

  // ---- epilogue: O /= l, write tf32 bits (row r -> head ha+(r>>6)) ----
  float inv[2][2];
  inv[0][0] = 1.0f / l_s[wm + gr];
  inv[0][1] = 1.0f / l_s[wm + 8 + gr];
  inv[1][0] = 1.0f / l_s[wm + 16 + gr];
  inv[1][1] = 1.0f / l_s[wm + 24 + gr];
  #pragma unroll
  for (int mt = 0; mt < 2; mt++)
    #pragma unroll
    for (int half = 0; half < 2; half++) {
      int r = wm + mt * 16 + gr + half * 8;
      int head = ha + (r >> 6);
      int qg = q0 + (r & 63);
      #pragma unroll
      for (int nt = 0; nt < 8; nt++) {
        int c = wn * 64 + nt * 8 + 2 * tg;
        uint2 w;
        w.x = f2tf(o[mt][nt][half * 2 + 0] * inv[mt][half]);
        w.y = f2tf(o[mt][nt][half * 2 + 1] * inv[mt][half]);
        *(uint2*)&Out[(size_t)qg * DMODEL + head * HD + c] = w;
      }
    }
}

// ---------------------------------------------------------------------------
// Launch
// ---------------------------------------------------------------------------
extern "C" void kernel_launch(void* const* d_in, const int* in_sizes, int n_in,
                              void* d_out, int out_size) {
  const float* x       = (const float*)d_in[0];
  const float* rope    = (const float*)d_in[1];
  // d_in[2] = mask: unused (causality implemented exactly in-kernel)
  const float* cache_k = (const float*)d_in[3];
  const float* cache_v = (const float*)d_in[4];
  const float* wq      = (const float*)d_in[5];
  const float* wk      = (const float*)d_in[6];
  const float* wv      = (const float*)d_in[7];
  const float* wo      = (const float*)d_in[8];
  float* out = (float*)d_out;

  unsigned *q, *k, *v, *ao, *xc, *wqc, *wkc, *wvc, *woc, *ckc, *cvc;
  cudaGetSymbolAddress((void**)&q,   g_q);
  cudaGetSymbolAddress((void**)&k,   g_k);
  cudaGetSymbolAddress((void**)&v,   g_v);
  cudaGetSymbolAddress((void**)&ao,  g_ao);
  cudaGetSymbolAddress((void**)&xc,  g_xc);
  cudaGetSymbolAddress((void**)&wqc, g_wqc);
  cudaGetSymbolAddress((void**)&wkc, g_wkc);
  cudaGetSymbolAddress((void**)&wvc, g_wvc);
  cudaGetSymbolAddress((void**)&woc, g_woc);
  cudaGetSymbolAddress((void**)&ckc, g_ckc);
  cudaGetSymbolAddress((void**)&cvc, g_cvc);

  cudaFuncSetAttribute(gemm_qkv, cudaFuncAttributeMaxDynamicSharedMemorySize,
                       GEMM_SMEM);
  cudaFuncSetAttribute(gemm_mma, cudaFuncAttributeMaxDynamicSharedMemorySize,
                       GEMM_SMEM);
  cudaFuncSetAttribute(attn_mma, cudaFuncAttributeMaxDynamicSharedMemorySize,
                       ATTN_SMEM_BYTES);

  // Batched conversions (2 launches)
  conv_all<<<12288, 256>>>(x, cache_k, cache_v, xc, ckc, cvc);
  convT_all<<<40960, 256>>>(wq, wk, wv, wo, wqc, wkc, wvc, woc);

  // Fused QKV projection (packed: 512 Q + 128 K + 128 V)
  gemm_qkv<<<768, 256, GEMM_SMEM>>>(xc, wqc, wkc, wvc, q, k, v, rope);

  // Flash attention (GQA 2-heads/CTA, cp.async K staging)
  attn_mma<<<512, 256, ATTN_SMEM_BYTES>>>(q, k, v, ckc, cvc, ao);

  // Output projection
  gemm_mma<<<dim3(DMODEL / 128, S_LEN / 128), 256, GEMM_SMEM>>>(
      ao, woc, out, DMODEL, DMODEL);
}